// round 11
// baseline (speedup 1.0000x reference)
#include <cuda_runtime.h>
#include <math.h>
#include <stdint.h>

#define Bb 64
#define Ss 256
#define Vv 32000
#define Ee 1024
#define Hh 1024
#define N4 4096

// ---- static device scratch ----
__device__ __align__(1024) float g_xproj[67108864UL];  // [m=s*64+b][n=g*1024+h]
__device__ float g_hb[2][65536];                       // h double buffer [b][h]
__device__ float g_c[65536];                           // cell state [b][h]
__device__ float g_bias3[N4];                          // bx+bg+bh, n = g*1024+h

typedef unsigned long long ull;

// packed fp32 FMA (B300 FFMA2): d.lo += a.lo*b.lo; d.hi += a.hi*b.hi
__device__ __forceinline__ void fma2(ull& d, ull a, ull b) {
    asm("fma.rn.f32x2 %0, %1, %2, %0;" : "+l"(d) : "l"(a), "l"(b));
}
__device__ __forceinline__ void unpack2(float& x, float& y, ull v) {
    asm("mov.b64 {%0, %1}, %2;" : "=f"(x), "=f"(y) : "l"(v));
}

// ---------------------------------------------------------------------------
__global__ void init_kernel() {
    int i = blockIdx.x * blockDim.x + threadIdx.x;
    if (i < 65536) { g_hb[0][i] = 0.f; g_c[i] = 0.f; }
}

__global__ void bias3_k(const float* __restrict__ bx, const float* __restrict__ bg,
                        const float* __restrict__ bh) {
    int n = blockIdx.x * blockDim.x + threadIdx.x;
    if (n < N4) g_bias3[n] = bx[n] + bg[n] + bh[n];
}

// ---------------------------------------------------------------------------
// xproj (R1 structure, f32x2 inner loop): g_xproj[m][n] = emb @ Wx + bias3.
// CTA 128m x 128n, 256 threads, per-thread 8m x 8n (as 4 m-pairs x 8 n).
__global__ __launch_bounds__(256) void xproj_f2(
    const int* __restrict__ X, const float* __restrict__ C,
    const float* __restrict__ Wx)
{
    __shared__ __align__(16) float As[8][128];
    __shared__ __align__(16) float Bs2[8][256];   // n duplicated: [k][2n],[2n+1]
    __shared__ int tok_s[128];

    const int bm = blockIdx.y << 7;
    const int bn = blockIdx.x << 7;
    const int gate = bn >> 10;
    const int h0 = bn & 1023;
    const float* __restrict__ Wg = Wx + (size_t)gate * Ee * Hh;
    const int tid = threadIdx.x;

    if (tid < 128) {
        int mg = bm + tid;
        tok_s[tid] = X[(mg & 63) * Ss + (mg >> 6)];
    }
    __syncthreads();

    const int tm = (tid >> 4) << 3;
    const int tn = (tid & 15) << 3;
    const int am = tid >> 1;
    const int ak = (tid & 1) << 2;
    const int bk = tid >> 5;
    const int bnl = (tid & 31) << 2;

    ull acc2[4][8];
#pragma unroll
    for (int p = 0; p < 4; p++)
#pragma unroll
        for (int j = 0; j < 8; j++) acc2[p][j] = 0ULL;

    const float* __restrict__ aptr = C + (size_t)tok_s[am] * Ee + ak;

    for (int k0 = 0; k0 < Ee; k0 += 8) {
        float4 av = *(const float4*)(aptr + k0);
        float4 bv = *(const float4*)(Wg + (size_t)(k0 + bk) * Hh + h0 + bnl);
        __syncthreads();
        As[ak + 0][am] = av.x;
        As[ak + 1][am] = av.y;
        As[ak + 2][am] = av.z;
        As[ak + 3][am] = av.w;
        *(float4*)(&Bs2[bk][2 * bnl])     = make_float4(bv.x, bv.x, bv.y, bv.y);
        *(float4*)(&Bs2[bk][2 * bnl + 4]) = make_float4(bv.z, bv.z, bv.w, bv.w);
        __syncthreads();
#pragma unroll
        for (int kk = 0; kk < 8; kk++) {
            const ulonglong2* ap = (const ulonglong2*)(&As[kk][tm]);
            ulonglong2 au = ap[0], av2 = ap[1];
            ull a2[4] = {au.x, au.y, av2.x, av2.y};   // m-pairs (tm,tm+1)..(tm+6,tm+7)
            const ulonglong2* bp = (const ulonglong2*)(&Bs2[kk][2 * tn]);
            ulonglong2 b0 = bp[0], b1 = bp[1], b2 = bp[2], b3 = bp[3];
            ull b[8] = {b0.x, b0.y, b1.x, b1.y, b2.x, b2.y, b3.x, b3.y};
#pragma unroll
            for (int p = 0; p < 4; p++)
#pragma unroll
                for (int j = 0; j < 8; j++)
                    fma2(acc2[p][j], a2[p], b[j]);
        }
    }

#pragma unroll
    for (int p = 0; p < 4; p++) {
        size_t r0 = (size_t)(bm + tm + 2 * p) * N4;
#pragma unroll
        for (int j = 0; j < 8; j++) {
            int n = bn + tn + j;
            float v0, v1;
            unpack2(v0, v1, acc2[p][j]);
            float bb = g_bias3[n];
            g_xproj[r0 + n]      = v0 + bb;
            g_xproj[r0 + N4 + n] = v1 + bb;
        }
    }
}

// ---------------------------------------------------------------------------
// Fused LSTM step: one kernel per t. 128 CTAs x 128 thr.
// CTA nb owns h in [nb*8, nb*8+8) x 4 gates for all 64 b. Full K=1024 per CTA.
// Thread: b-pair (2L,2L+1) x 2 h x 4 gates; f32x2 over the b-pair.
#define SK 32
__global__ __launch_bounds__(128) void lstm_step(const float* __restrict__ Wh, int t)
{
    __shared__ __align__(16) float As[SK][64];    // [k][b] h values
    __shared__ __align__(16) float Bs2[SK][68];   // [k][2c] dup weights, c = hl*4+g

    const int tid = threadIdx.x, nb = blockIdx.x;
    const int hb = nb * 8;
    const float* __restrict__ hin = g_hb[t & 1];
    float* __restrict__ hout = g_hb[(t + 1) & 1];

    const int L = tid & 31, hp = tid >> 5;        // b-pair, h-pair
    // A loader: thread (lb, lhalf) loads 4 float4 of h[lb][...]
    const int lb = tid >> 1, lhalf = tid & 1;
    const float* asrc = hin + lb * 1024 + lhalf * 16;
    // B loader: thread (lg, lk) loads Wh[lg][k0+lk][hb..hb+8)
    const int lg = tid >> 5, lk = tid & 31;
    const float* bsrc = Wh + (size_t)lg * 1048576 + hb;

    ull acc2[2][4];
#pragma unroll
    for (int e = 0; e < 2; e++)
#pragma unroll
        for (int g = 0; g < 4; g++) acc2[e][g] = 0ULL;

    for (int k0 = 0; k0 < 1024; k0 += SK) {
        float4 av[4];
#pragma unroll
        for (int q = 0; q < 4; q++)
            av[q] = *(const float4*)(asrc + k0 + q * 4);
        const float* brow = bsrc + (size_t)(k0 + lk) * 1024;
        float4 bv0 = *(const float4*)(brow);
        float4 bv1 = *(const float4*)(brow + 4);
        __syncthreads();
#pragma unroll
        for (int q = 0; q < 4; q++) {
            int ks = lhalf * 16 + q * 4;
            As[ks + 0][lb] = av[q].x;
            As[ks + 1][lb] = av[q].y;
            As[ks + 2][lb] = av[q].z;
            As[ks + 3][lb] = av[q].w;
        }
        float bw[8] = {bv0.x, bv0.y, bv0.z, bv0.w, bv1.x, bv1.y, bv1.z, bv1.w};
#pragma unroll
        for (int i = 0; i < 8; i++) {
            int c2 = (i * 4 + lg) * 2;
            Bs2[lk][c2]     = bw[i];
            Bs2[lk][c2 + 1] = bw[i];
        }
        __syncthreads();
#pragma unroll
        for (int k = 0; k < SK; k++) {
            ull a2 = *(const ull*)(&As[k][2 * L]);           // (h[2L], h[2L+1])
            const ulonglong2* wp = (const ulonglong2*)(&Bs2[k][16 * hp]);
            ulonglong2 w0 = wp[0], w1 = wp[1], w2 = wp[2], w3 = wp[3];
            fma2(acc2[0][0], a2, w0.x);
            fma2(acc2[0][1], a2, w0.y);
            fma2(acc2[0][2], a2, w1.x);
            fma2(acc2[0][3], a2, w1.y);
            fma2(acc2[1][0], a2, w2.x);
            fma2(acc2[1][1], a2, w2.y);
            fma2(acc2[1][2], a2, w3.x);
            fma2(acc2[1][3], a2, w3.y);
        }
    }

    // epilogue: LSTM cell for 4 cells (2 b x 2 h)
    const float* __restrict__ xp = g_xproj + (size_t)t * 64 * N4;
#pragma unroll
    for (int e = 0; e < 2; e++) {
        int h = hb + hp * 2 + e;
        float gb0[4], gb1[4];
#pragma unroll
        for (int g = 0; g < 4; g++) unpack2(gb0[g], gb1[g], acc2[e][g]);
#pragma unroll
        for (int bi = 0; bi < 2; bi++) {
            int b = 2 * L + bi;
            const float* gs = bi ? gb1 : gb0;
            const float* xr = xp + (size_t)b * N4;
            float gi = gs[0] + xr[h];
            float gf = gs[1] + xr[1024 + h];
            float go = gs[2] + xr[2048 + h];
            float gc = gs[3] + xr[3072 + h];
            float vi = 1.f / (1.f + expf(-gi));
            float vf = 1.f / (1.f + expf(-gf));
            float vo = 1.f / (1.f + expf(-go));
            int idx = b * 1024 + h;
            float c = vf * g_c[idx] + vi * tanhf(gc);
            g_c[idx] = c;
            hout[idx] = vo * tanhf(c);
        }
    }
}

// ---------------------------------------------------------------------------
// out[b, v] = h @ Wout + bout (R1 verbatim, reads g_hb[0]).
__global__ __launch_bounds__(256) void out_kernel(
    const float* __restrict__ Wout, const float* __restrict__ bout,
    float* __restrict__ out)
{
    __shared__ float Asm[16][64];
    __shared__ float Bsm[16][128];
    const int bn = blockIdx.x << 7;
    const int tid = threadIdx.x;
    const int tm = (tid >> 4) << 2, tn = (tid & 15) << 3;
    const int am = tid >> 2, ak = (tid & 3) << 2;
    const int bk = tid >> 4, bnl = (tid & 15) << 3;

    float acc[4][8];
#pragma unroll
    for (int i = 0; i < 4; i++)
#pragma unroll
        for (int j = 0; j < 8; j++) acc[i][j] = 0.f;

    const float* __restrict__ hsrc = g_hb[0];

    for (int k0 = 0; k0 < Hh; k0 += 16) {
        float4 av = *(const float4*)(hsrc + am * Hh + k0 + ak);
        const float* wr = Wout + (size_t)(k0 + bk) * Vv + bn + bnl;
        float4 b0 = *(const float4*)(wr);
        float4 b1 = *(const float4*)(wr + 4);
        __syncthreads();
        Asm[ak + 0][am] = av.x; Asm[ak + 1][am] = av.y;
        Asm[ak + 2][am] = av.z; Asm[ak + 3][am] = av.w;
        *(float4*)(&Bsm[bk][bnl])     = b0;
        *(float4*)(&Bsm[bk][bnl + 4]) = b1;
        __syncthreads();
#pragma unroll
        for (int kk = 0; kk < 16; kk++) {
            float a[4], b[8];
            *(float4*)(a)     = *(const float4*)(&Asm[kk][tm]);
            *(float4*)(b)     = *(const float4*)(&Bsm[kk][tn]);
            *(float4*)(b + 4) = *(const float4*)(&Bsm[kk][tn + 4]);
#pragma unroll
            for (int i = 0; i < 4; i++)
#pragma unroll
                for (int j = 0; j < 8; j++)
                    acc[i][j] = fmaf(a[i], b[j], acc[i][j]);
        }
    }
#pragma unroll
    for (int i = 0; i < 4; i++) {
        size_t ro = (size_t)(tm + i) * Vv + bn + tn;
#pragma unroll
        for (int j = 0; j < 8; j++)
            out[ro + j] = acc[i][j] + bout[bn + tn + j];
    }
}

// ---------------------------------------------------------------------------
extern "C" void kernel_launch(void* const* d_in, const int* in_sizes, int n_in,
                              void* d_out, int out_size)
{
    const int*   X    = (const int*)d_in[0];
    const float* C    = (const float*)d_in[1];
    const float* Wx   = (const float*)d_in[2];
    const float* bx   = (const float*)d_in[3];
    const float* Wh   = (const float*)d_in[4];
    const float* bh   = (const float*)d_in[5];
    const float* bg   = (const float*)d_in[6];
    const float* Wout = (const float*)d_in[7];
    const float* bout = (const float*)d_in[8];
    float* out = (float*)d_out;

    init_kernel<<<256, 256>>>();
    bias3_k<<<16, 256>>>(bx, bg, bh);
    xproj_f2<<<dim3(N4 / 128, (Ss * Bb) / 128), 256>>>(X, C, Wx);

    for (int t = 0; t < Ss; t++)
        lstm_step<<<128, 128>>>(Wh, t);

    out_kernel<<<Vv / 128, 256>>>(Wout, bout, out);
}

// round 12
// speedup vs baseline: 1.4927x; 1.4927x over previous
#include <cuda_runtime.h>
#include <math.h>
#include <stdint.h>

#define Bb 64
#define Ss 256
#define Vv 32000
#define Ee 1024
#define Hh 1024
#define N4 4096

// ---- static device scratch ----
__device__ __align__(1024) float g_xproj[67108864UL];  // [m=s*64+b][n=g*1024+h] (incl. all biases)
__device__ float g_hb[2][65536];                       // h double buffer [b][h]
__device__ float g_c[65536];                           // cell state [b][h]
__device__ float g_bias3[N4];                          // bx+bg+bh, n = g*1024+h

// ---------------------------------------------------------------------------
__global__ void init_kernel() {
    int i = blockIdx.x * blockDim.x + threadIdx.x;
    if (i < 65536) { g_hb[0][i] = 0.f; g_c[i] = 0.f; }
}

__global__ void bias3_k(const float* __restrict__ bx, const float* __restrict__ bg,
                        const float* __restrict__ bh) {
    int n = blockIdx.x * blockDim.x + threadIdx.x;
    if (n < N4) g_bias3[n] = bx[n] + bg[n] + bh[n];
}

// ---------------------------------------------------------------------------
// xproj (R1-verified structure): g_xproj[m][n] = emb @ Wx + (bx+bg+bh).
// CTA 128m x 128n, 256 threads, per-thread 8x8.
__global__ __launch_bounds__(256) void xproj_kernel(
    const int* __restrict__ X, const float* __restrict__ C,
    const float* __restrict__ Wx)
{
    __shared__ float As[8][128];
    __shared__ float Bs[8][128];
    __shared__ int tok_s[128];

    const int bm = blockIdx.y << 7;
    const int bn = blockIdx.x << 7;
    const int gate = bn >> 10;
    const int h0 = bn & 1023;
    const float* __restrict__ Wg = Wx + (size_t)gate * Ee * Hh;
    const int tid = threadIdx.x;

    if (tid < 128) {
        int mg = bm + tid;
        tok_s[tid] = X[(mg & 63) * Ss + (mg >> 6)];
    }
    __syncthreads();

    const int tm = (tid >> 4) << 3;
    const int tn = (tid & 15) << 3;
    const int am = tid >> 1;
    const int ak = (tid & 1) << 2;
    const int bk = tid >> 5;
    const int bnl = (tid & 31) << 2;

    float acc[8][8];
#pragma unroll
    for (int i = 0; i < 8; i++)
#pragma unroll
        for (int j = 0; j < 8; j++) acc[i][j] = 0.f;

    const float* __restrict__ aptr = C + (size_t)tok_s[am] * Ee + ak;

    for (int k0 = 0; k0 < Ee; k0 += 8) {
        float4 av = *(const float4*)(aptr + k0);
        float4 bv = *(const float4*)(Wg + (size_t)(k0 + bk) * Hh + h0 + bnl);
        __syncthreads();
        As[ak + 0][am] = av.x;
        As[ak + 1][am] = av.y;
        As[ak + 2][am] = av.z;
        As[ak + 3][am] = av.w;
        *(float4*)(&Bs[bk][bnl]) = bv;
        __syncthreads();
#pragma unroll
        for (int kk = 0; kk < 8; kk++) {
            float a[8], b[8];
            *(float4*)(a)     = *(const float4*)(&As[kk][tm]);
            *(float4*)(a + 4) = *(const float4*)(&As[kk][tm + 4]);
            *(float4*)(b)     = *(const float4*)(&Bs[kk][tn]);
            *(float4*)(b + 4) = *(const float4*)(&Bs[kk][tn + 4]);
#pragma unroll
            for (int i = 0; i < 8; i++)
#pragma unroll
                for (int j = 0; j < 8; j++)
                    acc[i][j] = fmaf(a[i], b[j], acc[i][j]);
        }
    }

#pragma unroll
    for (int i = 0; i < 8; i++) {
        size_t ro = (size_t)(bm + tm + i) * N4;
#pragma unroll
        for (int j = 0; j < 8; j++) {
            int n = bn + tn + j;
            g_xproj[ro + n] = acc[i][j] + g_bias3[n];
        }
    }
}

// ---------------------------------------------------------------------------
// Fused LSTM step (one launch per t). 128 CTAs x 256 thr.
// CTA nb owns h in [hb, hb+8) x 4 gates x all 64 b; full K=1024, chunks of 32.
// Thread tile: 4 b x 2 c (c = g*8 + hl). Epilogue: gates -> smem -> LSTM cell.
__global__ __launch_bounds__(256, 1) void lstm_step(const float* __restrict__ Wh, int t)
{
    __shared__ float As[32][68];   // [k][b], padded
    __shared__ float Bs[32][36];   // [k][c], c = g*8 + j, padded

    const int tid = threadIdx.x, nb = blockIdx.x;
    const int hb = nb << 3;
    const float* __restrict__ hin = g_hb[t & 1];
    float* __restrict__ hout = g_hb[(t + 1) & 1];

    // compute mapping
    const int bt = tid & 15;        // b0 = bt*4
    const int nt = tid >> 4;        // c0 = nt*2
    const int b0 = bt << 2;
    const int c0 = nt << 1;

    // A loader: thread (lb, lk8) loads hin[lb][k0+lk8 .. +7]
    const int lb = tid >> 2;
    const int lk8 = (tid & 3) << 3;
    const float* __restrict__ asrc = hin + lb * 1024 + lk8;

    // B loader: thread (lg, lk, lj4) loads Wh[lg][k0+lk][hb+lj4 .. +3]
    const int lg = tid >> 6;
    const int lk = (tid & 63) >> 1;
    const int lj4 = (tid & 1) << 2;
    const float* __restrict__ bsrc = Wh + (size_t)lg * 1048576 + hb + lj4;
    const int bc = (lg << 3) + lj4;

    float acc[4][2];
#pragma unroll
    for (int i = 0; i < 4; i++) { acc[i][0] = 0.f; acc[i][1] = 0.f; }

    for (int k0 = 0; k0 < 1024; k0 += 32) {
        float4 a0 = *(const float4*)(asrc + k0);
        float4 a1 = *(const float4*)(asrc + k0 + 4);
        float4 wv = *(const float4*)(bsrc + (size_t)(k0 + lk) * 1024);
        __syncthreads();
        As[lk8 + 0][lb] = a0.x; As[lk8 + 1][lb] = a0.y;
        As[lk8 + 2][lb] = a0.z; As[lk8 + 3][lb] = a0.w;
        As[lk8 + 4][lb] = a1.x; As[lk8 + 5][lb] = a1.y;
        As[lk8 + 6][lb] = a1.z; As[lk8 + 7][lb] = a1.w;
        *(float4*)(&Bs[lk][bc]) = wv;
        __syncthreads();
#pragma unroll
        for (int k = 0; k < 32; k++) {
            float a[4];
            *(float4*)(a) = *(const float4*)(&As[k][b0]);
            float2 bv = *(const float2*)(&Bs[k][c0]);
#pragma unroll
            for (int i = 0; i < 4; i++) {
                acc[i][0] = fmaf(a[i], bv.x, acc[i][0]);
                acc[i][1] = fmaf(a[i], bv.y, acc[i][1]);
            }
        }
    }

    // epilogue: stage gates in smem as gbuf[c][b] (reuse As storage)
    float* gbuf = &As[0][0];       // 32*64 = 2048 floats fit in As
    __syncthreads();
#pragma unroll
    for (int j = 0; j < 2; j++)
#pragma unroll
        for (int i = 0; i < 4; i++)
            gbuf[(c0 + j) * 64 + (b0 + i)] = acc[i][j];
    __syncthreads();

    const float* __restrict__ xp = g_xproj + (size_t)t * Bb * N4;
#pragma unroll
    for (int cc = 0; cc < 2; cc++) {
        int cell = tid + (cc << 8);    // 0..511
        int b = cell & 63, hl = cell >> 6;
        int h = hb + hl;
        const float* xr = xp + (size_t)b * N4 + h;
        float gi = gbuf[(hl)      * 64 + b] + xr[0];
        float gf = gbuf[(8 + hl)  * 64 + b] + xr[1024];
        float go = gbuf[(16 + hl) * 64 + b] + xr[2048];
        float gc = gbuf[(24 + hl) * 64 + b] + xr[3072];
        float vi = 1.f / (1.f + expf(-gi));
        float vf = 1.f / (1.f + expf(-gf));
        float vo = 1.f / (1.f + expf(-go));
        int idx = b * 1024 + h;
        float c = vf * g_c[idx] + vi * tanhf(gc);
        g_c[idx] = c;
        hout[idx] = vo * tanhf(c);
    }
}

// ---------------------------------------------------------------------------
// out[b, v] = h @ Wout + bout (R1 verbatim, reads g_hb[0]).
__global__ __launch_bounds__(256) void out_kernel(
    const float* __restrict__ Wout, const float* __restrict__ bout,
    float* __restrict__ out)
{
    __shared__ float Asm[16][64];
    __shared__ float Bsm[16][128];
    const int bn = blockIdx.x << 7;
    const int tid = threadIdx.x;
    const int tm = (tid >> 4) << 2, tn = (tid & 15) << 3;
    const int am = tid >> 2, ak = (tid & 3) << 2;
    const int bk = tid >> 4, bnl = (tid & 15) << 3;

    float acc[4][8];
#pragma unroll
    for (int i = 0; i < 4; i++)
#pragma unroll
        for (int j = 0; j < 8; j++) acc[i][j] = 0.f;

    const float* __restrict__ hsrc = g_hb[0];

    for (int k0 = 0; k0 < Hh; k0 += 16) {
        float4 av = *(const float4*)(hsrc + am * Hh + k0 + ak);
        const float* wr = Wout + (size_t)(k0 + bk) * Vv + bn + bnl;
        float4 b0 = *(const float4*)(wr);
        float4 b1 = *(const float4*)(wr + 4);
        __syncthreads();
        Asm[ak + 0][am] = av.x; Asm[ak + 1][am] = av.y;
        Asm[ak + 2][am] = av.z; Asm[ak + 3][am] = av.w;
        *(float4*)(&Bsm[bk][bnl])     = b0;
        *(float4*)(&Bsm[bk][bnl + 4]) = b1;
        __syncthreads();
#pragma unroll
        for (int kk = 0; kk < 16; kk++) {
            float a[4], b[8];
            *(float4*)(a)     = *(const float4*)(&Asm[kk][tm]);
            *(float4*)(b)     = *(const float4*)(&Bsm[kk][tn]);
            *(float4*)(b + 4) = *(const float4*)(&Bsm[kk][tn + 4]);
#pragma unroll
            for (int i = 0; i < 4; i++)
#pragma unroll
                for (int j = 0; j < 8; j++)
                    acc[i][j] = fmaf(a[i], b[j], acc[i][j]);
        }
    }
#pragma unroll
    for (int i = 0; i < 4; i++) {
        size_t ro = (size_t)(tm + i) * Vv + bn + tn;
#pragma unroll
        for (int j = 0; j < 8; j++)
            out[ro + j] = acc[i][j] + bout[bn + tn + j];
    }
}

// ---------------------------------------------------------------------------
extern "C" void kernel_launch(void* const* d_in, const int* in_sizes, int n_in,
                              void* d_out, int out_size)
{
    const int*   X    = (const int*)d_in[0];
    const float* C    = (const float*)d_in[1];
    const float* Wx   = (const float*)d_in[2];
    const float* bx   = (const float*)d_in[3];
    const float* Wh   = (const float*)d_in[4];
    const float* bh   = (const float*)d_in[5];
    const float* bg   = (const float*)d_in[6];
    const float* Wout = (const float*)d_in[7];
    const float* bout = (const float*)d_in[8];
    float* out = (float*)d_out;

    init_kernel<<<256, 256>>>();
    bias3_k<<<16, 256>>>(bx, bg, bh);
    xproj_kernel<<<dim3(N4 / 128, (Ss * Bb) / 128), 256>>>(X, C, Wx);

    for (int t = 0; t < Ss; t++)
        lstm_step<<<128, 256>>>(Wh, t);

    out_kernel<<<Vv / 128, 256>>>(Wout, bout, out);
}

// round 13
// speedup vs baseline: 1.8291x; 1.2254x over previous
#include <cuda_runtime.h>
#include <cuda_fp16.h>
#include <math.h>
#include <stdint.h>

#define Bb 64
#define Ss 256
#define Vv 32000
#define Ee 1024
#define Hh 1024
#define N4 4096
#define NSPLIT 4
#define KCH (Hh / NSPLIT)

// ---- static device scratch ----
__device__ __align__(1024) float  g_xproj[67108864UL];   // [m=s*64+b][n=g*1024+h]
__device__ __align__(1024) __half g_emb16[16777216];      // [m][k] fp16 gathered emb
__device__ __align__(1024) __half g_Wx16[4194304];        // [g][k][h] fp16 copy of Wx
__device__ float g_h[Bb * Hh];
__device__ float g_c[Bb * Hh];
__device__ float g_part[NSPLIT * Bb * N4];
__device__ float g_bias2[N4];   // bx+bg, n = g*1024+h  (bh added in step_act, as in R1)

// ---------------------------------------------------------------------------
__global__ void init_kernel() {
    int idx = blockIdx.x * blockDim.x + threadIdx.x;
    if (idx < Bb * Hh) { g_h[idx] = 0.f; g_c[idx] = 0.f; }
}

__global__ void bias2_k(const float* __restrict__ bx, const float* __restrict__ bg) {
    int n = blockIdx.x * blockDim.x + threadIdx.x;
    if (n < N4) g_bias2[n] = bx[n] + bg[n];
}

// gather + fp16 convert embeddings: g_emb16[m][k], m = s*64+b
__global__ void conv_emb16(const int* __restrict__ X, const float* __restrict__ C) {
    size_t g = (size_t)blockIdx.x * 256 + threadIdx.x;   // 4 elems per thread
    int m = (int)(g >> 8), ks = (int)(g & 255) << 2;
    int tok = X[(m & 63) * Ss + (m >> 6)];
    float4 v = *(const float4*)(C + (size_t)tok * 1024 + ks);
    __half h4[4] = {__float2half(v.x), __float2half(v.y),
                    __float2half(v.z), __float2half(v.w)};
    *(uint2*)(g_emb16 + (size_t)m * 1024 + ks) = *(uint2*)h4;
}

// elementwise fp32 -> fp16 copy of Wx (layout preserved: [g][k][h], k-major)
__global__ void conv_wx16(const float* __restrict__ Wx) {
    size_t i = ((size_t)blockIdx.x * 256 + threadIdx.x) << 2;
    float4 v = *(const float4*)(Wx + i);
    __half h4[4] = {__float2half(v.x), __float2half(v.y),
                    __float2half(v.z), __float2half(v.w)};
    *(uint2*)(g_Wx16 + i) = *(uint2*)h4;
}

// ---------------------------------------------------------------------------
// xproj via HFMA2: g_xproj[m][n] = emb @ Wx + (bx+bg).
// R1 tiling: CTA 128m x 128n, 256 threads, thread tile 8m x 8n (4 half2 n-pairs).
// fp16 accumulators flushed to fp32 every 16 K-chunks (128 k).
__global__ __launch_bounds__(256) void xproj_h2(
    const int* __restrict__ X, const float* __restrict__ C, int unused)
{
    __shared__ __half2 As2[8][128];   // [k][m] duplicated half2 (broadcast of a[m])
    __shared__ __half  Bs[8][128];    // [k][n] natural fp16

    const int bm = blockIdx.y << 7;
    const int bn = blockIdx.x << 7;
    const int gate = bn >> 10;
    const int h0 = bn & 1023;
    const __half* __restrict__ Wg = g_Wx16 + (size_t)gate * Ee * Hh;
    const int tid = threadIdx.x;

    const int tm = (tid >> 4) << 3;
    const int tn = (tid & 15) << 3;
    const int am = tid >> 1;          // 0..127
    const int ak = (tid & 1) << 2;    // 0 or 4
    const int bk = tid >> 5;          // 0..7
    const int bnl = (tid & 31) << 2;  // 0..124

    const __half* __restrict__ aptr = g_emb16 + (size_t)(bm + am) * Ee + ak;
    const __half* __restrict__ bptr = Wg + (size_t)bk * Hh + h0 + bnl;

    float accf[8][8];
#pragma unroll
    for (int i = 0; i < 8; i++)
#pragma unroll
        for (int j = 0; j < 8; j++) accf[i][j] = 0.f;

    __half2 acc2[8][4];
#pragma unroll
    for (int i = 0; i < 8; i++)
#pragma unroll
        for (int j = 0; j < 4; j++) acc2[i][j] = __float2half2_rn(0.f);

    for (int ch = 0; ch < 128; ch++) {
        const int k0 = ch << 3;
        uint2 au = *(const uint2*)(aptr + k0);
        uint2 bu = *(const uint2*)(bptr + (size_t)k0 * Hh);
        __syncthreads();
        {
            __half va[4];
            *(uint2*)va = au;
            As2[ak + 0][am] = __half2half2(va[0]);
            As2[ak + 1][am] = __half2half2(va[1]);
            As2[ak + 2][am] = __half2half2(va[2]);
            As2[ak + 3][am] = __half2half2(va[3]);
            *(uint2*)(&Bs[bk][bnl]) = bu;
        }
        __syncthreads();
#pragma unroll
        for (int kk = 0; kk < 8; kk++) {
            __half2 a2[8], b2[4];
            *(uint4*)(a2)     = *(const uint4*)(&As2[kk][tm]);
            *(uint4*)(a2 + 4) = *(const uint4*)(&As2[kk][tm + 4]);
            *(uint4*)(b2)     = *(const uint4*)(&Bs[kk][tn]);
#pragma unroll
            for (int i = 0; i < 8; i++)
#pragma unroll
                for (int j = 0; j < 4; j++)
                    acc2[i][j] = __hfma2(a2[i], b2[j], acc2[i][j]);
        }
        if ((ch & 15) == 15) {   // flush fp16 accumulators to fp32
#pragma unroll
            for (int i = 0; i < 8; i++)
#pragma unroll
                for (int j = 0; j < 4; j++) {
                    float2 f = __half22float2(acc2[i][j]);
                    accf[i][2 * j]     += f.x;
                    accf[i][2 * j + 1] += f.y;
                    acc2[i][j] = __float2half2_rn(0.f);
                }
        }
    }

#pragma unroll
    for (int i = 0; i < 8; i++) {
        size_t ro = (size_t)(bm + tm + i) * N4;
#pragma unroll
        for (int j = 0; j < 8; j++) {
            int n = bn + tn + j;
            g_xproj[ro + n] = accf[i][j] + g_bias2[n];
        }
    }
}

// ---------------------------------------------------------------------------
// R1-verified fp32 recurrence (verbatim): split-K step GEMM + activation.
__global__ __launch_bounds__(256) void step_gemm(const float* __restrict__ Wh)
{
    __shared__ float As[16][64];
    __shared__ float Bs[16][128];

    const int bn = blockIdx.x << 7;
    const int split = blockIdx.y;
    const int kbase = split * KCH;
    const int gate = bn >> 10;
    const int h0 = bn & 1023;
    const float* __restrict__ Wg = Wh + (size_t)gate * Hh * Hh;
    const int tid = threadIdx.x;

    const int tm = (tid >> 4) << 2;
    const int tn = (tid & 15) << 3;
    const int am = tid >> 2;
    const int ak = (tid & 3) << 2;
    const int bk = tid >> 4;
    const int bnl = (tid & 15) << 3;

    float acc[4][8];
#pragma unroll
    for (int i = 0; i < 4; i++)
#pragma unroll
        for (int j = 0; j < 8; j++) acc[i][j] = 0.f;

    for (int k0 = 0; k0 < KCH; k0 += 16) {
        float4 av = *(const float4*)(g_h + am * Hh + kbase + k0 + ak);
        const float* wrow = Wg + (size_t)(kbase + k0 + bk) * Hh + h0 + bnl;
        float4 bv0 = *(const float4*)(wrow);
        float4 bv1 = *(const float4*)(wrow + 4);
        __syncthreads();
        As[ak + 0][am] = av.x;
        As[ak + 1][am] = av.y;
        As[ak + 2][am] = av.z;
        As[ak + 3][am] = av.w;
        *(float4*)(&Bs[bk][bnl])     = bv0;
        *(float4*)(&Bs[bk][bnl + 4]) = bv1;
        __syncthreads();
#pragma unroll
        for (int kk = 0; kk < 16; kk++) {
            float a[4], b[8];
            *(float4*)(a)     = *(const float4*)(&As[kk][tm]);
            *(float4*)(b)     = *(const float4*)(&Bs[kk][tn]);
            *(float4*)(b + 4) = *(const float4*)(&Bs[kk][tn + 4]);
#pragma unroll
            for (int i = 0; i < 4; i++)
#pragma unroll
                for (int j = 0; j < 8; j++)
                    acc[i][j] = fmaf(a[i], b[j], acc[i][j]);
        }
    }

#pragma unroll
    for (int i = 0; i < 4; i++) {
        size_t ro = ((size_t)split * Bb + (tm + i)) * N4 + bn + tn;
#pragma unroll
        for (int j = 0; j < 8; j++)
            g_part[ro + j] = acc[i][j];
    }
}

__global__ void step_act(const float* __restrict__ bh, int t)
{
    int idx = blockIdx.x * blockDim.x + threadIdx.x;
    int b = idx >> 10;
    int k = idx & 1023;
    const float* __restrict__ xp = g_xproj + ((size_t)t * Bb + b) * N4;

    float g[4];
#pragma unroll
    for (int gg = 0; gg < 4; gg++) {
        int n = gg * Hh + k;
        float s = xp[n] + bh[n];
#pragma unroll
        for (int p = 0; p < NSPLIT; p++)
            s += g_part[((size_t)p * Bb + b) * N4 + n];
        g[gg] = s;
    }
    float vi = 1.f / (1.f + expf(-g[0]));
    float vf = 1.f / (1.f + expf(-g[1]));
    float vo = 1.f / (1.f + expf(-g[2]));
    float c  = vf * g_c[idx] + vi * tanhf(g[3]);
    g_c[idx] = c;
    g_h[idx] = vo * tanhf(c);
}

// ---------------------------------------------------------------------------
__global__ __launch_bounds__(256) void out_kernel(
    const float* __restrict__ Wout, const float* __restrict__ bout,
    float* __restrict__ out)
{
    __shared__ float Asm[16][64];
    __shared__ float Bsm[16][128];
    const int bn = blockIdx.x << 7;
    const int tid = threadIdx.x;
    const int tm = (tid >> 4) << 2, tn = (tid & 15) << 3;
    const int am = tid >> 2, ak = (tid & 3) << 2;
    const int bk = tid >> 4, bnl = (tid & 15) << 3;

    float acc[4][8];
#pragma unroll
    for (int i = 0; i < 4; i++)
#pragma unroll
        for (int j = 0; j < 8; j++) acc[i][j] = 0.f;

    for (int k0 = 0; k0 < Hh; k0 += 16) {
        float4 av = *(const float4*)(g_h + am * Hh + k0 + ak);
        const float* wr = Wout + (size_t)(k0 + bk) * Vv + bn + bnl;
        float4 b0 = *(const float4*)(wr);
        float4 b1 = *(const float4*)(wr + 4);
        __syncthreads();
        Asm[ak + 0][am] = av.x; Asm[ak + 1][am] = av.y;
        Asm[ak + 2][am] = av.z; Asm[ak + 3][am] = av.w;
        *(float4*)(&Bsm[bk][bnl])     = b0;
        *(float4*)(&Bsm[bk][bnl + 4]) = b1;
        __syncthreads();
#pragma unroll
        for (int kk = 0; kk < 16; kk++) {
            float a[4], b[8];
            *(float4*)(a)     = *(const float4*)(&Asm[kk][tm]);
            *(float4*)(b)     = *(const float4*)(&Bsm[kk][tn]);
            *(float4*)(b + 4) = *(const float4*)(&Bsm[kk][tn + 4]);
#pragma unroll
            for (int i = 0; i < 4; i++)
#pragma unroll
                for (int j = 0; j < 8; j++)
                    acc[i][j] = fmaf(a[i], b[j], acc[i][j]);
        }
    }
#pragma unroll
    for (int i = 0; i < 4; i++) {
        size_t ro = (size_t)(tm + i) * Vv + bn + tn;
#pragma unroll
        for (int j = 0; j < 8; j++)
            out[ro + j] = acc[i][j] + bout[bn + tn + j];
    }
}

// ---------------------------------------------------------------------------
extern "C" void kernel_launch(void* const* d_in, const int* in_sizes, int n_in,
                              void* d_out, int out_size)
{
    const int*   X    = (const int*)d_in[0];
    const float* C    = (const float*)d_in[1];
    const float* Wx   = (const float*)d_in[2];
    const float* bx   = (const float*)d_in[3];
    const float* Wh   = (const float*)d_in[4];
    const float* bh   = (const float*)d_in[5];
    const float* bg   = (const float*)d_in[6];
    const float* Wout = (const float*)d_in[7];
    const float* bout = (const float*)d_in[8];
    float* out = (float*)d_out;

    init_kernel<<<(Bb * Hh + 255) / 256, 256>>>();
    bias2_k<<<16, 256>>>(bx, bg);
    conv_emb16<<<16384, 256>>>(X, C);
    conv_wx16<<<4096, 256>>>(Wx);
    xproj_h2<<<dim3(32, 128), 256>>>(X, C, 0);

    for (int t = 0; t < Ss; t++) {
        step_gemm<<<dim3(N4 / 128, NSPLIT), 256>>>(Wh);
        step_act<<<(Bb * Hh + 255) / 256, 256>>>(bh, t);
    }

    out_kernel<<<Vv / 128, 256>>>(Wout, bout, out);
}

// round 16
// speedup vs baseline: 3.6010x; 1.9688x over previous
#include <cuda_runtime.h>
#include <cuda_fp16.h>
#include <math.h>
#include <stdint.h>

#define Bb 64
#define Ss 256
#define Vv 32000
#define Ee 1024
#define Hh 1024
#define N4 4096
#define NSPLIT 4

// ---- static device scratch (ONLY referenced inside kernels, never as host args) ----
__device__ __align__(1024) float  g_xproj[67108864UL];   // [m=s*64+b][n=g*1024+h]
__device__ __align__(1024) __half g_emb16[16777216];      // [m][k]
__device__ __align__(1024) __half g_Wx16n[4194304];       // [n=g*1024+h][k]
__device__ __align__(1024) __half g_Wh16n[4194304];       // [n=g*1024+h][k]
__device__ __align__(1024) __half g_h16[65536];           // h fp16 [b][k]
__device__ float g_h[Bb * Hh];
__device__ float g_c[Bb * Hh];
__device__ float g_part[NSPLIT * Bb * N4];
__device__ float g_bias3[N4];   // bx+bg+bh

// fp16 mma.sync m16n8k16, fp32 accum. A row-major [m][k], B "col" = [n][k].
#define MMA16816(d, a0, a1, a2, a3, b0, b1) \
    asm volatile("mma.sync.aligned.m16n8k16.row.col.f32.f16.f16.f32 " \
        "{%0,%1,%2,%3}, {%4,%5,%6,%7}, {%8,%9}, {%0,%1,%2,%3};" \
        : "+f"((d)[0]), "+f"((d)[1]), "+f"((d)[2]), "+f"((d)[3]) \
        : "r"(a0), "r"(a1), "r"(a2), "r"(a3), "r"(b0), "r"(b1))

// ---------------------------------------------------------------------------
__global__ void init_kernel() {
    int i = blockIdx.x * blockDim.x + threadIdx.x;
    if (i < Bb * Hh) {
        g_h[i] = 0.f; g_c[i] = 0.f;
        g_h16[i] = __float2half(0.f);
    }
}

__global__ void bias3_k(const float* __restrict__ bx, const float* __restrict__ bg,
                        const float* __restrict__ bh) {
    int n = blockIdx.x * blockDim.x + threadIdx.x;
    if (n < N4) g_bias3[n] = bx[n] + bg[n] + bh[n];
}

// gather + fp16 convert embeddings (R13-proven; internal dst)
__global__ void conv_emb16(const int* __restrict__ X, const float* __restrict__ C) {
    size_t g = (size_t)blockIdx.x * 256 + threadIdx.x;
    int m = (int)(g >> 8), ks = (int)(g & 255) << 2;
    int tok = X[(m & 63) * Ss + (m >> 6)];
    float4 v = *(const float4*)(C + (size_t)tok * 1024 + ks);
    __half h4[4] = {__float2half(v.x), __float2half(v.y),
                    __float2half(v.z), __float2half(v.w)};
    *(uint2*)(g_emb16 + (size_t)m * 1024 + ks) = *(uint2*)h4;
}

// transpose W [g][k][h] -> dst[n=g*1024+h][k] fp16; dst selected INTERNALLY.
__global__ void conv_wn16(const float* __restrict__ src, int which) {
    __shared__ float tile[32][33];
    __half* __restrict__ dst = which ? g_Wh16n : g_Wx16n;
    int tx = threadIdx.x, ty = threadIdx.y;
    int hb = blockIdx.x * 32, kb = blockIdx.y * 32, g = blockIdx.z;
    const float* s = src + (size_t)g * 1048576;
#pragma unroll
    for (int i = 0; i < 4; i++)
        tile[ty + i * 8][tx] = s[(size_t)(kb + ty + i * 8) * 1024 + hb + tx];
    __syncthreads();
#pragma unroll
    for (int i = 0; i < 4; i++) {
        int h = hb + ty + i * 8;
        size_t n = (size_t)g * 1024 + h;
        dst[n * 1024 + kb + tx] = __float2half(tile[tx][ty + i * 8]);
    }
}

// ---------------------------------------------------------------------------
// xproj fp16 MMA: g_xproj[m][n] = emb @ WxT + bias3.
// CTA 128m x 128n, 8 warps (wm2 x wn4), warp tile 64x32. R9-audited epilogue.
__global__ __launch_bounds__(256, 1) void xproj_mma16() {
    __shared__ float sD[64 * 130];
    const int tid = threadIdx.x, wid = tid >> 5, lane = tid & 31;
    const int wm = wid & 1, wn = wid >> 1;
    const int bm = blockIdx.y << 7, bn = blockIdx.x << 7;
    const int lr = lane >> 2, lc2 = (lane & 3) << 1;

    const __half* pA = g_emb16 + (size_t)(bm + wm * 64 + lr) * 1024 + lc2;
    const __half* pB = g_Wx16n + (size_t)(bn + wn * 32 + lr) * 1024 + lc2;

    float acc[4][4][4];
#pragma unroll
    for (int i = 0; i < 4; i++)
#pragma unroll
        for (int j = 0; j < 4; j++)
#pragma unroll
            for (int r = 0; r < 4; r++) acc[i][j][r] = 0.f;

#pragma unroll 1
    for (int k0 = 0; k0 < 1024; k0 += 16) {
        uint32_t A[4][4], B[4][2];
#pragma unroll
        for (int mt = 0; mt < 4; mt++) {
            const __half* p = pA + mt * 16384 + k0;
            A[mt][0] = *(const uint32_t*)(p);            // (m=lr,   k=lc2)
            A[mt][1] = *(const uint32_t*)(p + 8192);     // (m=lr+8, k=lc2)
            A[mt][2] = *(const uint32_t*)(p + 8);        // (m=lr,   k=lc2+8)
            A[mt][3] = *(const uint32_t*)(p + 8200);     // (m=lr+8, k=lc2+8)
        }
#pragma unroll
        for (int nt = 0; nt < 4; nt++) {
            const __half* q = pB + nt * 8192 + k0;
            B[nt][0] = *(const uint32_t*)(q);            // (n=lr, k=lc2)
            B[nt][1] = *(const uint32_t*)(q + 8);        // (n=lr, k=lc2+8)
        }
#pragma unroll
        for (int mt = 0; mt < 4; mt++)
#pragma unroll
            for (int nt = 0; nt < 4; nt++)
                MMA16816(acc[mt][nt], A[mt][0], A[mt][1], A[mt][2], A[mt][3],
                         B[nt][0], B[nt][1]);
    }

    // R9-audited epilogue: stage per 64-n half, store n = bn + half*64 + nl.
#pragma unroll
    for (int half = 0; half < 2; half++) {
        if ((wn >> 1) == half) {
#pragma unroll
            for (int mt = 0; mt < 4; mt++)
#pragma unroll
                for (int nt = 0; nt < 4; nt++) {
                    int nl = (wn & 1) * 32 + nt * 8 + lc2;
                    int ml = wm * 64 + mt * 16 + lr;
                    sD[nl * 130 + ml]           = acc[mt][nt][0];
                    sD[(nl + 1) * 130 + ml]     = acc[mt][nt][1];
                    sD[nl * 130 + ml + 8]       = acc[mt][nt][2];
                    sD[(nl + 1) * 130 + ml + 8] = acc[mt][nt][3];
                }
        }
        __syncthreads();
        for (int it = 0; it < 32; it++) {
            int idx = it * 256 + tid;
            int nl = idx & 63;
            int ml = idx >> 6;
            int n  = bn + half * 64 + nl;
            g_xproj[(size_t)(bm + ml) * 4096 + n] = sD[nl * 130 + ml] + g_bias3[n];
        }
        __syncthreads();
    }
}

// ---------------------------------------------------------------------------
// fp16 MMA split-K step GEMM: part[split][b][n] = sum_k h16[b,k]*Wh16n[n,k].
// Grid (32, NSPLIT), 256 thr, warp tile 64m x 16n (4x2 MMAs), no smem.
__global__ __launch_bounds__(256, 1) void step_mma16() {
    const int tid = threadIdx.x, wid = tid >> 5, lane = tid & 31;
    const int bn = blockIdx.x << 7;
    const int split = blockIdx.y;
    const int kbase = split << 8;          // K chunk of 256
    const int lr = lane >> 2, lc2 = (lane & 3) << 1;

    const __half* pA = g_h16 + (size_t)lr * 1024 + kbase + lc2;
    const __half* pB = g_Wh16n + (size_t)(bn + wid * 16 + lr) * 1024 + kbase + lc2;

    float acc[4][2][4];
#pragma unroll
    for (int i = 0; i < 4; i++)
#pragma unroll
        for (int j = 0; j < 2; j++)
#pragma unroll
            for (int r = 0; r < 4; r++) acc[i][j][r] = 0.f;

#pragma unroll 2
    for (int k0 = 0; k0 < 256; k0 += 16) {
        uint32_t A[4][4], B[2][2];
#pragma unroll
        for (int mt = 0; mt < 4; mt++) {
            const __half* p = pA + mt * 16384 + k0;
            A[mt][0] = *(const uint32_t*)(p);
            A[mt][1] = *(const uint32_t*)(p + 8192);
            A[mt][2] = *(const uint32_t*)(p + 8);
            A[mt][3] = *(const uint32_t*)(p + 8200);
        }
#pragma unroll
        for (int nt = 0; nt < 2; nt++) {
            const __half* q = pB + nt * 8192 + k0;
            B[nt][0] = *(const uint32_t*)(q);
            B[nt][1] = *(const uint32_t*)(q + 8);
        }
#pragma unroll
        for (int mt = 0; mt < 4; mt++)
#pragma unroll
            for (int nt = 0; nt < 2; nt++)
                MMA16816(acc[mt][nt], A[mt][0], A[mt][1], A[mt][2], A[mt][3],
                         B[nt][0], B[nt][1]);
    }

#pragma unroll
    for (int mt = 0; mt < 4; mt++)
#pragma unroll
        for (int nt = 0; nt < 2; nt++) {
            int row = mt * 16 + lr;                     // b
            int n = bn + wid * 16 + nt * 8 + lc2;
            size_t base = ((size_t)split * Bb + row) * N4 + n;
            g_part[base]              = acc[mt][nt][0];
            g_part[base + 1]          = acc[mt][nt][1];
            g_part[base + 8 * N4]     = acc[mt][nt][2];  // row+8
            g_part[base + 8 * N4 + 1] = acc[mt][nt][3];
        }
}

// ---------------------------------------------------------------------------
// reduce partials + LSTM cell (R1-proven structure; bh folded into xproj).
__global__ void step_act(int t)
{
    int idx = blockIdx.x * blockDim.x + threadIdx.x;
    int b = idx >> 10;
    int k = idx & 1023;
    const float* __restrict__ xp = g_xproj + ((size_t)t * Bb + b) * N4;

    float g[4];
#pragma unroll
    for (int gg = 0; gg < 4; gg++) {
        int n = gg * Hh + k;
        float s = xp[n];
#pragma unroll
        for (int p = 0; p < NSPLIT; p++)
            s += g_part[((size_t)p * Bb + b) * N4 + n];
        g[gg] = s;
    }
    float vi = 1.f / (1.f + expf(-g[0]));
    float vf = 1.f / (1.f + expf(-g[1]));
    float vo = 1.f / (1.f + expf(-g[2]));
    float c  = vf * g_c[idx] + vi * tanhf(g[3]);
    g_c[idx] = c;
    float h = vo * tanhf(c);
    g_h[idx] = h;
    g_h16[idx] = __float2half(h);
}

// ---------------------------------------------------------------------------
__global__ __launch_bounds__(256) void out_kernel(
    const float* __restrict__ Wout, const float* __restrict__ bout,
    float* __restrict__ out)
{
    __shared__ float Asm[16][64];
    __shared__ float Bsm[16][128];
    const int bn = blockIdx.x << 7;
    const int tid = threadIdx.x;
    const int tm = (tid >> 4) << 2, tn = (tid & 15) << 3;
    const int am = tid >> 2, ak = (tid & 3) << 2;
    const int bk = tid >> 4, bnl = (tid & 15) << 3;

    float acc[4][8];
#pragma unroll
    for (int i = 0; i < 4; i++)
#pragma unroll
        for (int j = 0; j < 8; j++) acc[i][j] = 0.f;

    for (int k0 = 0; k0 < Hh; k0 += 16) {
        float4 av = *(const float4*)(g_h + am * Hh + k0 + ak);
        const float* wr = Wout + (size_t)(k0 + bk) * Vv + bn + bnl;
        float4 b0 = *(const float4*)(wr);
        float4 b1 = *(const float4*)(wr + 4);
        __syncthreads();
        Asm[ak + 0][am] = av.x; Asm[ak + 1][am] = av.y;
        Asm[ak + 2][am] = av.z; Asm[ak + 3][am] = av.w;
        *(float4*)(&Bsm[bk][bnl])     = b0;
        *(float4*)(&Bsm[bk][bnl + 4]) = b1;
        __syncthreads();
#pragma unroll
        for (int kk = 0; kk < 16; kk++) {
            float a[4], b[8];
            *(float4*)(a)     = *(const float4*)(&Asm[kk][tm]);
            *(float4*)(b)     = *(const float4*)(&Bsm[kk][tn]);
            *(float4*)(b + 4) = *(const float4*)(&Bsm[kk][tn + 4]);
#pragma unroll
            for (int i = 0; i < 4; i++)
#pragma unroll
                for (int j = 0; j < 8; j++)
                    acc[i][j] = fmaf(a[i], b[j], acc[i][j]);
        }
    }
#pragma unroll
    for (int i = 0; i < 4; i++) {
        size_t ro = (size_t)(tm + i) * Vv + bn + tn;
#pragma unroll
        for (int j = 0; j < 8; j++)
            out[ro + j] = acc[i][j] + bout[bn + tn + j];
    }
}

// ---------------------------------------------------------------------------
extern "C" void kernel_launch(void* const* d_in, const int* in_sizes, int n_in,
                              void* d_out, int out_size)
{
    const int*   X    = (const int*)d_in[0];
    const float* C    = (const float*)d_in[1];
    const float* Wx   = (const float*)d_in[2];
    const float* bx   = (const float*)d_in[3];
    const float* Wh   = (const float*)d_in[4];
    const float* bh   = (const float*)d_in[5];
    const float* bg   = (const float*)d_in[6];
    const float* Wout = (const float*)d_in[7];
    const float* bout = (const float*)d_in[8];
    float* out = (float*)d_out;

    init_kernel<<<(Bb * Hh + 255) / 256, 256>>>();
    bias3_k<<<16, 256>>>(bx, bg, bh);
    conv_emb16<<<16384, 256>>>(X, C);
    conv_wn16<<<dim3(32, 32, 4), dim3(32, 8)>>>(Wx, 0);
    conv_wn16<<<dim3(32, 32, 4), dim3(32, 8)>>>(Wh, 1);
    xproj_mma16<<<dim3(32, 128), 256>>>();

    for (int t = 0; t < Ss; t++) {
        step_mma16<<<dim3(32, NSPLIT), 256>>>();
        step_act<<<(Bb * Hh + 255) / 256, 256>>>(t);
    }

    out_kernel<<<Vv / 128, 256>>>(Wout, bout, out);
}

// round 17
// speedup vs baseline: 4.1924x; 1.1642x over previous
#include <cuda_runtime.h>
#include <cuda_fp16.h>
#include <math.h>
#include <stdint.h>

#define Bb 64
#define Ss 256
#define Vv 32000
#define Ee 1024
#define Hh 1024
#define N4 4096

// ---- static device scratch (ONLY referenced inside kernels, never as host args) ----
__device__ __align__(1024) float  g_xproj[67108864UL];   // [m=s*64+b][n=g*1024+h]
__device__ __align__(1024) __half g_emb16[16777216];      // [m][k]
__device__ __align__(1024) __half g_Wx16n[4194304];       // [n=g*1024+h][k]
__device__ __align__(1024) __half g_Wh16n[4194304];       // [n=g*1024+h][k]
__device__ __align__(1024) __half g_h16[65536];           // h fp16 [b][k]
__device__ float g_h[Bb * Hh];
__device__ float g_c[Bb * Hh];
__device__ float g_bias3[N4];   // bx+bg+bh

// fp16 mma.sync m16n8k16, fp32 accum. A row-major [m][k], B "col" = [n][k].
#define MMA16816(d, a0, a1, a2, a3, b0, b1) \
    asm volatile("mma.sync.aligned.m16n8k16.row.col.f32.f16.f16.f32 " \
        "{%0,%1,%2,%3}, {%4,%5,%6,%7}, {%8,%9}, {%0,%1,%2,%3};" \
        : "+f"((d)[0]), "+f"((d)[1]), "+f"((d)[2]), "+f"((d)[3]) \
        : "r"(a0), "r"(a1), "r"(a2), "r"(a3), "r"(b0), "r"(b1))

// ---------------------------------------------------------------------------
__global__ void init_kernel() {
    int i = blockIdx.x * blockDim.x + threadIdx.x;
    if (i < Bb * Hh) {
        g_h[i] = 0.f; g_c[i] = 0.f;
        g_h16[i] = __float2half(0.f);
    }
}

__global__ void bias3_k(const float* __restrict__ bx, const float* __restrict__ bg,
                        const float* __restrict__ bh) {
    int n = blockIdx.x * blockDim.x + threadIdx.x;
    if (n < N4) g_bias3[n] = bx[n] + bg[n] + bh[n];
}

// gather + fp16 convert embeddings (proven)
__global__ void conv_emb16(const int* __restrict__ X, const float* __restrict__ C) {
    size_t g = (size_t)blockIdx.x * 256 + threadIdx.x;
    int m = (int)(g >> 8), ks = (int)(g & 255) << 2;
    int tok = X[(m & 63) * Ss + (m >> 6)];
    float4 v = *(const float4*)(C + (size_t)tok * 1024 + ks);
    __half h4[4] = {__float2half(v.x), __float2half(v.y),
                    __float2half(v.z), __float2half(v.w)};
    *(uint2*)(g_emb16 + (size_t)m * 1024 + ks) = *(uint2*)h4;
}

// transpose W [g][k][h] -> dst[n=g*1024+h][k] fp16; dst selected INTERNALLY (proven)
__global__ void conv_wn16(const float* __restrict__ src, int which) {
    __shared__ float tile[32][33];
    __half* __restrict__ dst = which ? g_Wh16n : g_Wx16n;
    int tx = threadIdx.x, ty = threadIdx.y;
    int hb = blockIdx.x * 32, kb = blockIdx.y * 32, g = blockIdx.z;
    const float* s = src + (size_t)g * 1048576;
#pragma unroll
    for (int i = 0; i < 4; i++)
        tile[ty + i * 8][tx] = s[(size_t)(kb + ty + i * 8) * 1024 + hb + tx];
    __syncthreads();
#pragma unroll
    for (int i = 0; i < 4; i++) {
        int h = hb + ty + i * 8;
        size_t n = (size_t)g * 1024 + h;
        dst[n * 1024 + kb + tx] = __float2half(tile[tx][ty + i * 8]);
    }
}

// ---------------------------------------------------------------------------
// xproj fp16 MMA (R16-proven, unchanged).
__global__ __launch_bounds__(256, 1) void xproj_mma16() {
    __shared__ float sD[64 * 130];
    const int tid = threadIdx.x, wid = tid >> 5, lane = tid & 31;
    const int wm = wid & 1, wn = wid >> 1;
    const int bm = blockIdx.y << 7, bn = blockIdx.x << 7;
    const int lr = lane >> 2, lc2 = (lane & 3) << 1;

    const __half* pA = g_emb16 + (size_t)(bm + wm * 64 + lr) * 1024 + lc2;
    const __half* pB = g_Wx16n + (size_t)(bn + wn * 32 + lr) * 1024 + lc2;

    float acc[4][4][4];
#pragma unroll
    for (int i = 0; i < 4; i++)
#pragma unroll
        for (int j = 0; j < 4; j++)
#pragma unroll
            for (int r = 0; r < 4; r++) acc[i][j][r] = 0.f;

#pragma unroll 1
    for (int k0 = 0; k0 < 1024; k0 += 16) {
        uint32_t A[4][4], B[4][2];
#pragma unroll
        for (int mt = 0; mt < 4; mt++) {
            const __half* p = pA + mt * 16384 + k0;
            A[mt][0] = *(const uint32_t*)(p);
            A[mt][1] = *(const uint32_t*)(p + 8192);
            A[mt][2] = *(const uint32_t*)(p + 8);
            A[mt][3] = *(const uint32_t*)(p + 8200);
        }
#pragma unroll
        for (int nt = 0; nt < 4; nt++) {
            const __half* q = pB + nt * 8192 + k0;
            B[nt][0] = *(const uint32_t*)(q);
            B[nt][1] = *(const uint32_t*)(q + 8);
        }
#pragma unroll
        for (int mt = 0; mt < 4; mt++)
#pragma unroll
            for (int nt = 0; nt < 4; nt++)
                MMA16816(acc[mt][nt], A[mt][0], A[mt][1], A[mt][2], A[mt][3],
                         B[nt][0], B[nt][1]);
    }

#pragma unroll
    for (int half = 0; half < 2; half++) {
        if ((wn >> 1) == half) {
#pragma unroll
            for (int mt = 0; mt < 4; mt++)
#pragma unroll
                for (int nt = 0; nt < 4; nt++) {
                    int nl = (wn & 1) * 32 + nt * 8 + lc2;
                    int ml = wm * 64 + mt * 16 + lr;
                    sD[nl * 130 + ml]           = acc[mt][nt][0];
                    sD[(nl + 1) * 130 + ml]     = acc[mt][nt][1];
                    sD[nl * 130 + ml + 8]       = acc[mt][nt][2];
                    sD[(nl + 1) * 130 + ml + 8] = acc[mt][nt][3];
                }
        }
        __syncthreads();
        for (int it = 0; it < 32; it++) {
            int idx = it * 256 + tid;
            int nl = idx & 63;
            int ml = idx >> 6;
            int n  = bn + half * 64 + nl;
            g_xproj[(size_t)(bm + ml) * 4096 + n] = sD[nl * 130 + ml] + g_bias3[n];
        }
        __syncthreads();
    }
}

// ---------------------------------------------------------------------------
// Fused LSTM step: GEMM (warp-split K) + smem reduction + activation, one launch.
// 128 CTAs x 256 thr. CTA nb owns h in [nb*8, nb*8+8) x 4 gates (nt = gate) x 64 b.
// Warp wid covers K chunk [wid*128, wid*128+128). red[w][gate*8+hl][b] pad 65.
#define SM_RED (8 * 2080 * 4)   // 66560 B
__global__ __launch_bounds__(256, 1) void lstm_fused(int t) {
    extern __shared__ float red[];
    const int tid = threadIdx.x, wid = tid >> 5, lane = tid & 31;
    const int nb = blockIdx.x;
    const int hb = nb << 3;
    const int kbase = wid << 7;
    const int lr = lane >> 2, lc2 = (lane & 3) << 1;

    const __half* pA = g_h16 + (size_t)lr * 1024 + kbase + lc2;

    float acc[4][4][4];
#pragma unroll
    for (int i = 0; i < 4; i++)
#pragma unroll
        for (int j = 0; j < 4; j++)
#pragma unroll
            for (int r = 0; r < 4; r++) acc[i][j][r] = 0.f;

#pragma unroll
    for (int ks = 0; ks < 128; ks += 16) {
        uint32_t A[4][4], B[4][2];
#pragma unroll
        for (int mt = 0; mt < 4; mt++) {
            const __half* p = pA + mt * 16384 + ks;
            A[mt][0] = *(const uint32_t*)(p);
            A[mt][1] = *(const uint32_t*)(p + 8192);
            A[mt][2] = *(const uint32_t*)(p + 8);
            A[mt][3] = *(const uint32_t*)(p + 8200);
        }
#pragma unroll
        for (int nt = 0; nt < 4; nt++) {   // nt = gate; rows n = nt*1024 + hb + lr
            const __half* q = g_Wh16n + (size_t)((nt << 10) + hb + lr) * 1024
                              + kbase + ks + lc2;
            B[nt][0] = *(const uint32_t*)(q);
            B[nt][1] = *(const uint32_t*)(q + 8);
        }
#pragma unroll
        for (int mt = 0; mt < 4; mt++)
#pragma unroll
            for (int nt = 0; nt < 4; nt++)
                MMA16816(acc[mt][nt], A[mt][0], A[mt][1], A[mt][2], A[mt][3],
                         B[nt][0], B[nt][1]);
    }

    // store warp partials: red[wid][nl = nt*8 + col][row = b] (validated d-mapping)
#pragma unroll
    for (int mt = 0; mt < 4; mt++)
#pragma unroll
        for (int nt = 0; nt < 4; nt++) {
            int row = mt * 16 + lr;
            int nl = nt * 8 + lc2;
            float* r = red + wid * 2080 + nl * 65 + row;
            r[0]      = acc[mt][nt][0];   // (row,   nl)
            r[65]     = acc[mt][nt][1];   // (row,   nl+1)
            r[8]      = acc[mt][nt][2];   // (row+8, nl)
            r[73]     = acc[mt][nt][3];   // (row+8, nl+1)
        }
    __syncthreads();

    // epilogue: 512 cells (64 b x 8 hl), 2 per thread
    const float* __restrict__ xp = g_xproj + (size_t)t * Bb * N4;
#pragma unroll
    for (int cc = 0; cc < 2; cc++) {
        int cell = tid + (cc << 8);
        int b = cell & 63, hl = cell >> 6;
        int h = hb + hl;
        const float* xr = xp + (size_t)b * N4 + h;
        float gs[4];
#pragma unroll
        for (int g = 0; g < 4; g++) {
            float s = xr[g << 10];
            int nl = (g << 3) + hl;
#pragma unroll
            for (int w = 0; w < 8; w++)
                s += red[w * 2080 + nl * 65 + b];
            gs[g] = s;
        }
        float vi = 1.f / (1.f + expf(-gs[0]));
        float vf = 1.f / (1.f + expf(-gs[1]));
        float vo = 1.f / (1.f + expf(-gs[2]));
        int idx = b * 1024 + h;
        float c = vf * g_c[idx] + vi * tanhf(gs[3]);
        g_c[idx] = c;
        float hv = vo * tanhf(c);
        g_h[idx] = hv;
        g_h16[idx] = __float2half(hv);
    }
}

// ---------------------------------------------------------------------------
__global__ __launch_bounds__(256) void out_kernel(
    const float* __restrict__ Wout, const float* __restrict__ bout,
    float* __restrict__ out)
{
    __shared__ float Asm[16][64];
    __shared__ float Bsm[16][128];
    const int bn = blockIdx.x << 7;
    const int tid = threadIdx.x;
    const int tm = (tid >> 4) << 2, tn = (tid & 15) << 3;
    const int am = tid >> 2, ak = (tid & 3) << 2;
    const int bk = tid >> 4, bnl = (tid & 15) << 3;

    float acc[4][8];
#pragma unroll
    for (int i = 0; i < 4; i++)
#pragma unroll
        for (int j = 0; j < 8; j++) acc[i][j] = 0.f;

    for (int k0 = 0; k0 < Hh; k0 += 16) {
        float4 av = *(const float4*)(g_h + am * Hh + k0 + ak);
        const float* wr = Wout + (size_t)(k0 + bk) * Vv + bn + bnl;
        float4 b0 = *(const float4*)(wr);
        float4 b1 = *(const float4*)(wr + 4);
        __syncthreads();
        Asm[ak + 0][am] = av.x; Asm[ak + 1][am] = av.y;
        Asm[ak + 2][am] = av.z; Asm[ak + 3][am] = av.w;
        *(float4*)(&Bsm[bk][bnl])     = b0;
        *(float4*)(&Bsm[bk][bnl + 4]) = b1;
        __syncthreads();
#pragma unroll
        for (int kk = 0; kk < 16; kk++) {
            float a[4], b[8];
            *(float4*)(a)     = *(const float4*)(&Asm[kk][tm]);
            *(float4*)(b)     = *(const float4*)(&Bsm[kk][tn]);
            *(float4*)(b + 4) = *(const float4*)(&Bsm[kk][tn + 4]);
#pragma unroll
            for (int i = 0; i < 4; i++)
#pragma unroll
                for (int j = 0; j < 8; j++)
                    acc[i][j] = fmaf(a[i], b[j], acc[i][j]);
        }
    }
#pragma unroll
    for (int i = 0; i < 4; i++) {
        size_t ro = (size_t)(tm + i) * Vv + bn + tn;
#pragma unroll
        for (int j = 0; j < 8; j++)
            out[ro + j] = acc[i][j] + bout[bn + tn + j];
    }
}

// ---------------------------------------------------------------------------
extern "C" void kernel_launch(void* const* d_in, const int* in_sizes, int n_in,
                              void* d_out, int out_size)
{
    const int*   X    = (const int*)d_in[0];
    const float* C    = (const float*)d_in[1];
    const float* Wx   = (const float*)d_in[2];
    const float* bx   = (const float*)d_in[3];
    const float* Wh   = (const float*)d_in[4];
    const float* bh   = (const float*)d_in[5];
    const float* bg   = (const float*)d_in[6];
    const float* Wout = (const float*)d_in[7];
    const float* bout = (const float*)d_in[8];
    float* out = (float*)d_out;

    cudaFuncSetAttribute(lstm_fused, cudaFuncAttributeMaxDynamicSharedMemorySize, SM_RED);

    init_kernel<<<(Bb * Hh + 255) / 256, 256>>>();
    bias3_k<<<16, 256>>>(bx, bg, bh);
    conv_emb16<<<16384, 256>>>(X, C);
    conv_wn16<<<dim3(32, 32, 4), dim3(32, 8)>>>(Wx, 0);
    conv_wn16<<<dim3(32, 32, 4), dim3(32, 8)>>>(Wh, 1);
    xproj_mma16<<<dim3(32, 128), 256>>>();

    for (int t = 0; t < Ss; t++)
        lstm_fused<<<128, 256, SM_RED>>>(t);

    out_kernel<<<Vv / 128, 256>>>(Wout, bout, out);
}